// round 16
// baseline (speedup 1.0000x reference)
#include <cuda_runtime.h>
#include <cuda_fp16.h>

// 24-qubit state-vector sim, 8 two-qubit gates, step s -> qubits (s, s+7).
// R16 = R15 rebalanced 4+4 gates, both passes fully structured:
//  Pass0 = gates 0..3, tile = amp bits 0..10 (contiguous, 2048 amps):
//    ph1 fused fp32-LDG + gate3(3,10) + STS
//    ph2 gate2(2,9) smem round trip
//    ph3 pair<0,1,7,8> (gates 0,1) + direct fp16 STG (uint4, L2 evict_last)
//  Pass1 = gates 4..7, tile = amp bits {0..7,11..14} (4096 amps, 32KB smem,
//          128 threads x 2 supergroups/phase):
//    ph1 fused fp16-LDG (L2 evict_first) + gate4(tile 4,8) + STS
//    ph2 gate7(tile 7,11) smem round trip
//    ph3 pair<5,6,9,10> (gates 5,6) + direct fp32 STG.32 (128B-coalesced)
// Swizzle folds x4->0b0101, x5->0b1010, x6->0b0011: GF(2) rank-4 verified for
// every 16-lane phase pattern of both passes.

#define NSTATE (1u << 24)
typedef unsigned long long u64;

static __device__ __align__(16) unsigned g_mid[1u << 24];   // half2 per amp, 64MB

__device__ __forceinline__ u64 pk2(float lo, float hi) {
    u64 r; asm("mov.b64 %0, {%1, %2};" : "=l"(r) : "f"(lo), "f"(hi)); return r;
}
__device__ __forceinline__ void upk2(u64 v, float& lo, float& hi) {
    asm("mov.b64 {%0, %1}, %2;" : "=f"(lo), "=f"(hi) : "l"(v));
}
__device__ __forceinline__ u64 ffma2(u64 a, u64 b, u64 c) {
    u64 d; asm("fma.rn.f32x2 %0, %1, %2, %3;" : "=l"(d) : "l"(a), "l"(b), "l"(c)); return d;
}
__device__ __forceinline__ u64 fmul2(u64 a, u64 b) {
    u64 d; asm("mul.rn.f32x2 %0, %1, %2;" : "=l"(d) : "l"(a), "l"(b)); return d;
}
__device__ __forceinline__ u64 fadd2(u64 a, u64 b) {
    u64 d; asm("add.rn.f32x2 %0, %1, %2;" : "=l"(d) : "l"(a), "l"(b)); return d;
}
__device__ __forceinline__ float negf(float v) {
    return __int_as_float(__float_as_int(v) ^ 0x80000000u);
}
__device__ __forceinline__ unsigned SWZ(unsigned x) {
    return x ^ (((x >> 4) & 1u) * 5u) ^ (((x >> 5) & 1u) * 10u)
             ^ (((x >> 6) & 1u) * 3u);
}

// ---- L2 residency policies ----
__device__ __forceinline__ u64 mkpol_evict_first() {
    u64 p; asm("createpolicy.fractional.L2::evict_first.b64 %0, 1.0;" : "=l"(p));
    return p;
}
__device__ __forceinline__ u64 mkpol_evict_last() {
    u64 p; asm("createpolicy.fractional.L2::evict_last.b64 %0, 1.0;" : "=l"(p));
    return p;
}
__device__ __forceinline__ float4 ldg_stream(const float* p, u64 pol) {
    float4 v;
    asm volatile("ld.global.nc.L2::cache_hint.v4.f32 {%0,%1,%2,%3}, [%4], %5;"
                 : "=f"(v.x), "=f"(v.y), "=f"(v.z), "=f"(v.w) : "l"(p), "l"(pol));
    return v;
}
__device__ __forceinline__ uint4 ldg_consume_u4(const unsigned* p, u64 pol) {
    uint4 v;
    asm volatile("ld.global.L2::cache_hint.v4.u32 {%0,%1,%2,%3}, [%4], %5;"
                 : "=r"(v.x), "=r"(v.y), "=r"(v.z), "=r"(v.w) : "l"(p), "l"(pol));
    return v;
}
__device__ __forceinline__ void stg_keep_u4(unsigned* p, uint4 v, u64 pol) {
    asm volatile("st.global.L2::cache_hint.v4.u32 [%0], {%1,%2,%3,%4}, %5;"
                 :: "l"(p), "r"(v.x), "r"(v.y), "r"(v.z), "r"(v.w), "l"(pol)
                 : "memory");
}

// half2 <-> packed float2 (u64)
__device__ __forceinline__ unsigned f2_to_h2(u64 v) {
    float lo, hi; upk2(v, lo, hi);
    __half2 h = __floats2half2_rn(lo, hi);
    return *reinterpret_cast<unsigned*>(&h);
}
__device__ __forceinline__ u64 h2_to_f2(unsigned u) {
    __half2 h = *reinterpret_cast<__half2*>(&u);
    float2 f = __half22float2(h);
    return pk2(f.x, f.y);
}

// Complex 4x4 gate on a quad; weights packed (wr,wi). Two-phase A/B form.
__device__ __forceinline__ void gate4(u64& v0, u64& v1, u64& v2, u64& v3,
                                      const u64* __restrict__ w)
{
    float r0,i0,r1,i1,r2,i2,r3,i3;
    upk2(v0,r0,i0); upk2(v1,r1,i1); upk2(v2,r2,i2); upk2(v3,r3,i3);

    u64 P0 = pk2(r0, r0), P1 = pk2(r1, r1), P2 = pk2(r2, r2), P3 = pk2(r3, r3);
    u64 A0 = fmul2(P0, w[0]);
    A0 = ffma2(P1, w[1], A0); A0 = ffma2(P2, w[2], A0); A0 = ffma2(P3, w[3], A0);
    u64 A1 = fmul2(P0, w[4]);
    A1 = ffma2(P1, w[5], A1); A1 = ffma2(P2, w[6], A1); A1 = ffma2(P3, w[7], A1);
    u64 A2 = fmul2(P0, w[8]);
    A2 = ffma2(P1, w[9], A2); A2 = ffma2(P2, w[10], A2); A2 = ffma2(P3, w[11], A2);
    u64 A3 = fmul2(P0, w[12]);
    A3 = ffma2(P1, w[13], A3); A3 = ffma2(P2, w[14], A3); A3 = ffma2(P3, w[15], A3);

    u64 Q0 = pk2(i0, i0), Q1 = pk2(i1, i1), Q2 = pk2(i2, i2), Q3 = pk2(i3, i3);
    {
        u64 B = fmul2(Q0, w[0]);
        B = ffma2(Q1, w[1], B); B = ffma2(Q2, w[2], B); B = ffma2(Q3, w[3], B);
        float bl, bh; upk2(B, bl, bh);
        v0 = fadd2(A0, pk2(negf(bh), bl));
    }
    {
        u64 B = fmul2(Q0, w[4]);
        B = ffma2(Q1, w[5], B); B = ffma2(Q2, w[6], B); B = ffma2(Q3, w[7], B);
        float bl, bh; upk2(B, bl, bh);
        v1 = fadd2(A1, pk2(negf(bh), bl));
    }
    {
        u64 B = fmul2(Q0, w[8]);
        B = ffma2(Q1, w[9], B); B = ffma2(Q2, w[10], B); B = ffma2(Q3, w[11], B);
        float bl, bh; upk2(B, bl, bh);
        v2 = fadd2(A2, pk2(negf(bh), bl));
    }
    {
        u64 B = fmul2(Q0, w[12]);
        B = ffma2(Q1, w[13], B); B = ffma2(Q2, w[14], B); B = ffma2(Q3, w[15], B);
        float bl, bh; upk2(B, bl, bh);
        v3 = fadd2(A3, pk2(negf(bh), bl));
    }
}

__device__ __forceinline__ unsigned expand2(unsigned t, int L, int H) {
    unsigned x = ((t & ~((1u << L) - 1u)) << 1) | (t & ((1u << L) - 1u));
    return ((x & ~((1u << H) - 1u)) << 1) | (x & ((1u << H) - 1u));
}
__device__ __forceinline__ unsigned expand4(unsigned t, int P0, int P1, int P2, int P3) {
    unsigned x = t;
    x = ((x & ~((1u << P0) - 1u)) << 1) | (x & ((1u << P0) - 1u));
    x = ((x & ~((1u << P1) - 1u)) << 1) | (x & ((1u << P1) - 1u));
    x = ((x & ~((1u << P2) - 1u)) << 1) | (x & ((1u << P2) - 1u));
    x = ((x & ~((1u << P3) - 1u)) << 1) | (x & ((1u << P3) - 1u));
    return x;
}

// Single gate round trip on quads at tile bits (L,H), NG groups per thread.
template <int L, int H, int NG, int NT>
__device__ __forceinline__ void apply_single(float2* sm, unsigned tid,
                                             const float* __restrict__ gp)
{
    u64 w[16];
    #pragma unroll
    for (int k = 0; k < 16; ++k)
        w[k] = pk2(__ldg(gp + k), __ldg(gp + 16 + k));

    #pragma unroll
    for (int k = 0; k < NG; ++k) {
        unsigned x = expand2(tid + (unsigned)NT * k, L, H);
        unsigned i0 = SWZ(x),             i1 = SWZ(x | (1u << L));
        unsigned i2 = SWZ(x | (1u << H)), i3 = SWZ(x | (1u << L) | (1u << H));
        float2 a = sm[i0], bb = sm[i1], c = sm[i2], d = sm[i3];
        u64 v0 = pk2(a.x, a.y), v1 = pk2(bb.x, bb.y);
        u64 v2 = pk2(c.x, c.y), v3 = pk2(d.x, d.y);
        gate4(v0, v1, v2, v3, w);
        float lo, hi;
        upk2(v0, lo, hi); sm[i0] = make_float2(lo, hi);
        upk2(v1, lo, hi); sm[i1] = make_float2(lo, hi);
        upk2(v2, lo, hi); sm[i2] = make_float2(lo, hi);
        upk2(v3, lo, hi); sm[i3] = make_float2(lo, hi);
    }
}

// ---- Pass 0: gates 0..3. Tile = amp bits 0..10 (contiguous); block -> 11..23 ----
__global__ __launch_bounds__(128, 5)
void qsim_pass0(const float* __restrict__ in, const float* __restrict__ gates)
{
    __shared__ float2 sm[2048];
    const unsigned t = threadIdx.x;
    const unsigned hi = blockIdx.x << 11;

    // ph1: fused fp32 LDG (stream) + gate3 (bits 3,10) + STS.
    {
        const u64 polF = mkpol_evict_first();
        u64 w[16];
        #pragma unroll
        for (int k = 0; k < 16; ++k)
            w[k] = pk2(__ldg(gates + 3 * 32 + k), __ldg(gates + 3 * 32 + 16 + k));

        const unsigned B = ((t & 1u) << 2) | ((t >> 1) << 4);  // tile {2,4..9}
        u64 p[16];
        #pragma unroll
        for (int q = 0; q < 4; ++q) {
            unsigned a0 = B | ((q & 1u) << 3) | ((unsigned)(q >> 1) << 10);
            unsigned g = hi | a0;
            float4 r4 = ldg_stream(in + g, polF);
            float4 m4 = ldg_stream(in + NSTATE + g, polF);
            p[q * 4 + 0] = pk2(r4.x, m4.x);
            p[q * 4 + 1] = pk2(r4.y, m4.y);
            p[q * 4 + 2] = pk2(r4.z, m4.z);
            p[q * 4 + 3] = pk2(r4.w, m4.w);
        }
        #pragma unroll
        for (int f = 0; f < 4; ++f)
            gate4(p[f], p[f + 4], p[f + 8], p[f + 12], w);
        #pragma unroll
        for (int i = 0; i < 16; ++i) {
            unsigned a = B | (unsigned)(i & 3)
                       | (((unsigned)(i >> 2) & 1u) << 3)
                       | (((unsigned)(i >> 3) & 1u) << 10);
            float lo, hic; upk2(p[i], lo, hic);
            sm[SWZ(a)] = make_float2(lo, hic);
        }
    }
    __syncthreads();

    // ph2: gate2 (bits 2,9), smem round trip.
    apply_single<2, 9, 4, 128>(sm, t, gates + 2 * 32);
    __syncthreads();

    // ph3: gates 0,1 (pair <0,1,7,8>) + direct fp16 STG pinned in L2.
    {
        const u64 polL = mkpol_evict_last();
        const unsigned x = expand4(t, 0, 1, 7, 8);
        u64 p[16];
        #pragma unroll
        for (int i = 0; i < 16; ++i) {
            unsigned off = (i & 3u) | (((i >> 2) & 1) << 7) | (((i >> 3) & 1) << 8);
            float2 v = sm[SWZ(x | off)];
            p[i] = pk2(v.x, v.y);
        }
        {   u64 w[16];
            #pragma unroll
            for (int k = 0; k < 16; ++k)
                w[k] = pk2(__ldg(gates + k), __ldg(gates + 16 + k));
            gate4(p[0],  p[1],  p[4],  p[5],  w);   // gate 0: vary i bits (0,2)
            gate4(p[2],  p[3],  p[6],  p[7],  w);
            gate4(p[8],  p[9],  p[12], p[13], w);
            gate4(p[10], p[11], p[14], p[15], w);
        }
        {   u64 w[16];
            #pragma unroll
            for (int k = 0; k < 16; ++k)
                w[k] = pk2(__ldg(gates + 32 + k), __ldg(gates + 48 + k));
            gate4(p[0], p[2], p[8],  p[10], w);     // gate 1: vary i bits (1,3)
            gate4(p[1], p[3], p[9],  p[11], w);
            gate4(p[4], p[6], p[12], p[14], w);
            gate4(p[5], p[7], p[13], p[15], w);
        }
        #pragma unroll
        for (int h = 0; h < 4; ++h) {
            unsigned bi = h << 2;
            unsigned a = x | ((h & 1u) << 7) | ((unsigned)(h >> 1) << 8);
            unsigned g = hi | a;
            uint4 u;
            u.x = f2_to_h2(p[bi + 0]);
            u.y = f2_to_h2(p[bi + 1]);
            u.z = f2_to_h2(p[bi + 2]);
            u.w = f2_to_h2(p[bi + 3]);
            stg_keep_u4(g_mid + g, u, polL);
        }
    }
}

// ---- Pass 1: gates 4..7. Tile = amp bits {0..7, 11..14} (4096 amps);
//      block bits -> amp {8,9,10, 15..23}. g(a) = hi | (a&255) | ((a>>8)<<11) ----
__global__ __launch_bounds__(128, 5)
void qsim_pass1(float* __restrict__ st, const float* __restrict__ gates)
{
    __shared__ float2 sm[4096];   // 32KB
    const unsigned t = threadIdx.x;
    const unsigned b = blockIdx.x;
    const unsigned hi = ((b & 7u) << 8) | ((b >> 3) << 15);

    // ph1: fused fp16 LDG (consume) + gate4 (amp 4,11 -> tile 4,8) + STS. 2 supergroups.
    {
        const u64 polF = mkpol_evict_first();
        u64 w[16];
        #pragma unroll
        for (int k = 0; k < 16; ++k)
            w[k] = pk2(__ldg(gates + 4 * 32 + k), __ldg(gates + 4 * 32 + 16 + k));

        #pragma unroll
        for (int s = 0; s < 2; ++s) {
            unsigned sg = t + 128u * s;   // 8 bits
            unsigned B = ((sg & 3u) << 2) | (((sg >> 2) & 7u) << 5) | ((sg >> 5) << 9);
            u64 p[16];
            #pragma unroll
            for (int q = 0; q < 4; ++q) {
                unsigned a0 = B | ((q & 1u) << 4) | ((unsigned)(q >> 1) << 8);
                unsigned g = hi | (a0 & 255u) | ((a0 >> 8) << 11);
                uint4 u = ldg_consume_u4(g_mid + g, polF);
                p[q * 4 + 0] = h2_to_f2(u.x);
                p[q * 4 + 1] = h2_to_f2(u.y);
                p[q * 4 + 2] = h2_to_f2(u.z);
                p[q * 4 + 3] = h2_to_f2(u.w);
            }
            #pragma unroll
            for (int f = 0; f < 4; ++f)
                gate4(p[f], p[f + 4], p[f + 8], p[f + 12], w);
            #pragma unroll
            for (int i = 0; i < 16; ++i) {
                unsigned a = B | (unsigned)(i & 3)
                           | (((unsigned)(i >> 2) & 1u) << 4)
                           | (((unsigned)(i >> 3) & 1u) << 8);
                float lo, hic; upk2(p[i], lo, hic);
                sm[SWZ(a)] = make_float2(lo, hic);
            }
        }
    }
    __syncthreads();

    // ph2: gate7 (amp 7,14 -> tile 7,11), smem round trip, 8 quad-groups.
    apply_single<7, 11, 8, 128>(sm, t, gates + 7 * 32);
    __syncthreads();

    // ph3: gates 5,6 (pair <5,6,9,10>) + direct fp32 STG.32. 2 supergroups.
    #pragma unroll
    for (int s = 0; s < 2; ++s) {
        const unsigned x = expand4(t + 128u * s, 5, 6, 9, 10);
        u64 p[16];
        #pragma unroll
        for (int i = 0; i < 16; ++i) {
            unsigned off = ((i & 1u) << 5) | (((i >> 1) & 1u) << 6)
                         | (((i >> 2) & 1u) << 9) | (((i >> 3) & 1u) << 10);
            float2 v = sm[SWZ(x | off)];
            p[i] = pk2(v.x, v.y);
        }
        {   u64 w[16];
            #pragma unroll
            for (int k = 0; k < 16; ++k)
                w[k] = pk2(__ldg(gates + 5 * 32 + k), __ldg(gates + 5 * 32 + 16 + k));
            gate4(p[0],  p[1],  p[4],  p[5],  w);   // gate 5: vary i bits (0,2)
            gate4(p[2],  p[3],  p[6],  p[7],  w);
            gate4(p[8],  p[9],  p[12], p[13], w);
            gate4(p[10], p[11], p[14], p[15], w);
        }
        {   u64 w[16];
            #pragma unroll
            for (int k = 0; k < 16; ++k)
                w[k] = pk2(__ldg(gates + 6 * 32 + k), __ldg(gates + 6 * 32 + 16 + k));
            gate4(p[0], p[2], p[8],  p[10], w);     // gate 6: vary i bits (1,3)
            gate4(p[1], p[3], p[9],  p[11], w);
            gate4(p[4], p[6], p[12], p[14], w);
            gate4(p[5], p[7], p[13], p[15], w);
        }
        #pragma unroll
        for (int i = 0; i < 16; ++i) {
            unsigned off = ((i & 1u) << 5) | (((i >> 1) & 1u) << 6)
                         | (((i >> 2) & 1u) << 9) | (((i >> 3) & 1u) << 10);
            unsigned a = x | off;
            unsigned g = hi | (a & 255u) | ((a >> 8) << 11);
            float lo, hic; upk2(p[i], lo, hic);
            st[g] = lo;
            st[NSTATE + g] = hic;
        }
    }
}

extern "C" void kernel_launch(void* const* d_in, const int* in_sizes, int n_in,
                              void* d_out, int out_size)
{
    const float* state = (const float*)d_in[0];   // 2 * 2^24 floats (re, im planes)
    const float* gates = (const float*)d_in[1];   // 8 * 2 * 4 * 4 floats
    float* out = (float*)d_out;

    qsim_pass0<<<8192, 128>>>(state, gates);   // gates 0..3 -> fp16 scratch
    qsim_pass1<<<4096, 128>>>(out, gates);     // gates 4..7 -> fp32 output
}